// round 10
// baseline (speedup 1.0000x reference)
#include <cuda_runtime.h>

// UniSURF-style renderer: per-ray sphere intersect + 32-step occupancy march
// + 8 secant iterations on a tiny MLP (3 -> 32 -> 1). One ray per thread.
//
//   occ logit z(d) = b2 + sum_j relu(A_j + d*R_j) * W2_j
//   A_j, W_j are LAUNCH constants -> kept in SMEM, loaded per eval via
//   ld.shared.v2.u64 (asm volatile, so they never occupy 64 registers).
//   Only R_j (ray.W1) stays in registers. Regs ~80 -> 10 blocks/SM.
//   Packed fp32x2 FMAs; dual-eval march; z cached in smem; predicated
//   first-crossing capture; warp-granular chunk scheduling (no divergence).

#define HID     32
#define NPAIR   16
#define NSTEPS  32
#define NSECANT 8
#define NEARV   0.5f
#define EPSV    1e-6f
#define THREADS 64
#define NBLK    1480         // 10 blocks/SM x 148 SMs, single wave

typedef unsigned long long ull;
typedef unsigned int uint32;

__device__ __forceinline__ ull pack2(float x, float y) {
    ull r;
    asm("mov.b64 %0, {%1, %2};" : "=l"(r) : "f"(x), "f"(y));
    return r;
}

__device__ __forceinline__ void unpack2(ull v, float& x, float& y) {
    asm("mov.b64 {%0, %1}, %2;" : "=f"(x), "=f"(y) : "l"(v));
}

__device__ __forceinline__ ull relu2(ull v) {
    float x, y;
    unpack2(v, x, y);
    return pack2(fmaxf(x, 0.0f), fmaxf(y, 0.0f));
}

__device__ __forceinline__ ull dup2(float d) {
    ull dd;
    asm("mov.b64 %0, {%1, %1};" : "=l"(dd) : "f"(d));
    return dd;
}

__device__ __forceinline__ ull fma2(ull a, ull b, ull c) {
    ull r;
    asm("fma.rn.f32x2 %0, %1, %2, %3;" : "=l"(r) : "l"(a), "l"(b), "l"(c));
    return r;
}

__device__ __forceinline__ float reduce2(ull a0, ull a1, float b2v) {
    ull s;
    asm("add.rn.f32x2 %0, %1, %2;" : "=l"(s) : "l"(a0), "l"(a1));
    float sx, sy;
    unpack2(s, sx, sy);
    return b2v + (sx + sy);
}

// load {A_pair, W_pair} from smem at byte offset OFFS (string literal)
#define LDAW(OFFS, Ak, Wk) \
    asm volatile("ld.shared.v2.u64 {%0, %1}, [%2+" OFFS "];" \
                 : "=l"(Ak), "=l"(Wk) : "r"(awb))

#define FORALL(M) M(0,"0") M(1,"16") M(2,"32") M(3,"48") M(4,"64") M(5,"80") \
    M(6,"96") M(7,"112") M(8,"128") M(9,"144") M(10,"160") M(11,"176") \
    M(12,"192") M(13,"208") M(14,"224") M(15,"240")

// single eval: z(d). 2 acc chains (a0,a1 by pair parity).
__device__ __forceinline__ float occ_z(float d, const ull* R, uint32 awb,
                                       float b2v) {
    const ull dd = dup2(d);
    ull a0 = 0ull, a1 = 0ull;
#define SSTEP(K, OFFS) { \
    ull Ak, Wk; LDAW(OFFS, Ak, Wk); \
    ull h = relu2(fma2(dd, R[K], Ak)); \
    if ((K) & 1) a1 = fma2(h, Wk, a1); else a0 = fma2(h, Wk, a0); }
    FORALL(SSTEP)
#undef SSTEP
    return reduce2(a0, a1, b2v);
}

// dual eval: z(da), z(db) together; A/W loads shared; 4 indep chains.
__device__ __forceinline__ void occ_z_dual(float da, float db, const ull* R,
                                           uint32 awb, float b2v,
                                           float& za, float& zb) {
    const ull dda = dup2(da);
    const ull ddb = dup2(db);
    ull a0 = 0ull, a1 = 0ull, b0 = 0ull, b1 = 0ull;
#define DSTEP(K, OFFS) { \
    ull Ak, Wk; LDAW(OFFS, Ak, Wk); \
    ull ha = relu2(fma2(dda, R[K], Ak)); \
    ull hb = relu2(fma2(ddb, R[K], Ak)); \
    if ((K) & 1) { a1 = fma2(ha, Wk, a1); b1 = fma2(hb, Wk, b1); } \
    else         { a0 = fma2(ha, Wk, a0); b0 = fma2(hb, Wk, b0); } }
    FORALL(DSTEP)
#undef DSTEP
    za = reduce2(a0, a1, b2v);
    zb = reduce2(b0, b1, b2v);
}

__device__ __forceinline__ float sigmoidf_(float z) {
    return 1.0f / (1.0f + __expf(-z));
}

__global__ void __launch_bounds__(THREADS, 10) unisurf_kernel(
    const float* __restrict__ cam, const float* __restrict__ dirs,
    const float* __restrict__ W1, const float* __restrict__ b1,
    const float* __restrict__ W2, const float* __restrict__ b2,
    float* __restrict__ out, int P)
{
    __shared__ float sW1[3][HID];
    __shared__ __align__(16) float sAW[NPAIR * 4];  // {A0,A1,W0,W1} x16
    __shared__ float sMisc[5];                       // cam0..2, b2, |cam|^2
    __shared__ float zbuf[NSTEPS][THREADS];          // march z cache

    const int tid = threadIdx.x;
    if (tid < HID) {
        const float c0 = cam[0], c1 = cam[1], c2 = cam[2];
        const float w0 = W1[tid], w1 = W1[HID + tid], w2 = W1[2 * HID + tid];
        sW1[0][tid] = w0;
        sW1[1][tid] = w1;
        sW1[2][tid] = w2;
        const float Aj = fmaf(c0, w0, fmaf(c1, w1, fmaf(c2, w2, b1[tid])));
        const int k = tid >> 1, h = tid & 1;
        sAW[k * 4 + h] = Aj;
        sAW[k * 4 + 2 + h] = W2[tid];
        if (tid == 0) {
            sMisc[0] = c0; sMisc[1] = c1; sMisc[2] = c2;
            sMisc[3] = b2[0];
            sMisc[4] = c0 * c0 + c1 * c1 + c2 * c2;
        }
    }
    __syncthreads();

    uint32 awb;
    asm("{ .reg .u64 t; cvta.to.shared.u64 t, %1; cvt.u32.u64 %0, t; }"
        : "=r"(awb) : "l"(sAW));

    const float c0 = sMisc[0], c1 = sMisc[1], c2 = sMisc[2];
    const float b2v = sMisc[3], cc = sMisc[4];
    const float stepc = 1.0f / (float)(NSTEPS - 1);

    // warp-granular chunk scheduling: chunks of 32 rays, warp-uniform.
    const int lane = tid & 31;
    const int gw = blockIdx.x * (THREADS / 32) + (tid >> 5);
    const int totalw = gridDim.x * (THREADS / 32);
    const int nchunks = (P + 31) >> 5;

    for (int c = gw; c < nchunks; c += totalw) {
        const int p = (c << 5) + lane;
        const int pc = p < P ? p : (P - 1);

        const float dx = dirs[3 * pc + 0];
        const float dy = dirs[3 * pc + 1];
        const float dz = dirs[3 * pc + 2];
        const float invn = rsqrtf(dx * dx + dy * dy + dz * dz);
        const float rx = dx * invn, ry = dy * invn, rz = dz * invn;

        const float rcd = rx * c0 + ry * c1 + rz * c2;
        const float under = rcd * rcd - (cc - 1.0f);   // radius = 1
        const bool hit = under > 0.0f;
        const float s = sqrtf(fmaxf(under, 0.0f));
        const float far = fmaxf(s - rcd, NEARV + EPSV);
        const float stepd = (far - NEARV) * stepc;     // incremental step

        // per-ray R_j = ray.W1_j, packed as fp32x2 pairs (only per-ray state)
        ull R[NPAIR];
#pragma unroll
        for (int k = 0; k < NPAIR; k++) {
            const int j = 2 * k;
            const float r0 = fmaf(rx, sW1[0][j],
                             fmaf(ry, sW1[1][j], rz * sW1[2][j]));
            const float r1 = fmaf(rx, sW1[0][j + 1],
                             fmaf(ry, sW1[1][j + 1], rz * sW1[2][j + 1]));
            R[k] = pack2(r0, r1);
        }

        // coarse march, two evals at a time; cache z in smem; capture first
        // free->occupied crossing with predicated selects.
        int  idx = 0;
        bool found = false;
        float zprev = occ_z(NEARV, R, awb, b2v);    // sample 0 (d = NEAR)
        zbuf[0][tid] = zprev;
        float d = NEARV;
#pragma unroll 1
        for (int i = 1; i <= NSTEPS - 3; i += 2) {  // i = 1,3,...,29
            const float da = d + stepd;
            const float db = da + stepd;
            float za, zb;
            occ_z_dual(da, db, R, awb, b2v, za, zb);
            zbuf[i][tid] = za;
            zbuf[i + 1][tid] = zb;
            const bool ca = (zprev < 0.0f) && (za >= 0.0f);
            const bool cb = (za < 0.0f) && (zb >= 0.0f);
            idx = (!found && ca) ? (i - 1) : idx;
            found |= ca;
            idx = (!found && cb) ? i : idx;
            found |= cb;
            zprev = zb;
            d = db;
        }
        {   // final sample i = 31
            const float dcur = d + stepd;
            const float z = occ_z(dcur, R, awb, b2v);
            zbuf[NSTEPS - 1][tid] = z;
            const bool cl = (zprev < 0.0f) && (z >= 0.0f);
            idx = (!found && cl) ? (NSTEPS - 2) : idx;
            found |= cl;
        }

        float dpred = 0.0f, osurf = 0.0f;
        const bool ok = found && hit;

        if (ok) {
            // brackets via the exact reference formula; z from the cache
            const float tl = (float)idx * stepc;
            const float th = (float)(idx + 1) * stepc;
            float dl = fmaf(far, tl, NEARV * (1.0f - tl));
            float dh = fmaf(far, th, NEARV * (1.0f - th));
            float fl = sigmoidf_(zbuf[idx][tid]) - 0.5f;
            float fh = sigmoidf_(zbuf[idx + 1][tid]) - 0.5f;

#pragma unroll 1
            for (int it = 0; it < NSECANT; it++) {
                float den = fh - fl;
                if (fabsf(den) < EPSV) den = EPSV;
                const float dm = dl - __fdividef(fl * (dh - dl), den);
                const float fm = sigmoidf_(occ_z(dm, R, awb, b2v)) - 0.5f;
                if (fm < 0.0f) { dl = dm; fl = fm; }
                else           { dh = dm; fh = fm; }
            }
            float den = fh - fl;
            if (fabsf(den) < EPSV) den = EPSV;
            dpred = dl - __fdividef(fl * (dh - dl), den);
            osurf = sigmoidf_(occ_z(dpred, R, awb, b2v));
        }

        if (p < P) {
            out[p] = dpred;
            out[P + p] = osurf;
        }
    }
}

extern "C" void kernel_launch(void* const* d_in, const int* in_sizes, int n_in,
                              void* d_out, int out_size)
{
    const float* cam  = (const float*)d_in[0];
    const float* dirs = (const float*)d_in[1];
    const float* W1   = (const float*)d_in[2];
    const float* b1   = (const float*)d_in[3];
    const float* W2   = (const float*)d_in[4];
    const float* b2   = (const float*)d_in[5];
    float* out = (float*)d_out;

    const int P = in_sizes[1] / 3;
    const int nchunks = (P + 31) >> 5;
    int blocks = NBLK;
    const int maxb = (nchunks + 1) / 2;   // 2 warps per block
    if (blocks > maxb) blocks = maxb;
    if (blocks < 1) blocks = 1;
    unisurf_kernel<<<blocks, THREADS>>>(cam, dirs, W1, b1, W2, b2, out, P);
}